// round 14
// baseline (speedup 1.0000x reference)
#include <cuda_runtime.h>
#include <cuda_bf16.h>
#include <math.h>

// ------------------------------------------------------------------
// Static scratch (no allocations allowed anywhere)
// ------------------------------------------------------------------
#define MAX_T     3900000
#define MAX_REG   1024
#define REG_CAP   128
#define PERCAP    6144
#define MAX_PEAKS 131072
#define MAX_OPS   (1<<18)
#define H1BINS    (1<<19)
#define H2BINS    (1<<12)

__device__ float g_x[MAX_T];
__device__ float g_f0[MAX_T];
__device__ float g_f0m[MAX_T];

__device__ unsigned g_h1[H1BINS];
__device__ unsigned g_h2[H2BINS];

__device__ double   g_sum;
__device__ float    g_meanf;
__device__ unsigned g_gpeak_bits;
__device__ float    g_gpeak;
__device__ unsigned long long g_npos;
__device__ unsigned g_h1bin;
__device__ unsigned long long g_k2;
__device__ float    g_m32;
__device__ unsigned g_minf0m_bits;
__device__ double   g_maxw;

__device__ int g_nstarts, g_nends;
__device__ int g_starts[MAX_REG], g_ends[MAX_REG];
__device__ int g_R;
__device__ int g_tail;

__device__ int g_lcnt[REG_CAP];
__device__ int g_rcnt[REG_CAP];
__device__ int g_lpos[REG_CAP][PERCAP];
__device__ int g_lw[REG_CAP][PERCAP];
__device__ int g_rpos[REG_CAP][PERCAP];

__device__ int g_npeaks;
__device__ int g_peaks[MAX_PEAKS];

__device__ int  g_nops;
__device__ int4 g_ops[MAX_OPS];   // (dst0, src0, n, hann_len)

// ------------------------------------------------------------------
// Small kernels
// ------------------------------------------------------------------
__global__ void k_init() {
    int i = blockIdx.x * blockDim.x + threadIdx.x;
    int stride = gridDim.x * blockDim.x;
    for (int j = i; j < H1BINS; j += stride) g_h1[j] = 0u;
    for (int j = i; j < H2BINS; j += stride) g_h2[j] = 0u;
    for (int j = i; j < REG_CAP; j += stride) { g_lcnt[j] = 0; g_rcnt[j] = 0; }
    if (i == 0) {
        g_sum = 0.0; g_gpeak_bits = 0u; g_npos = 0ull;
        g_nstarts = 0; g_nends = 0; g_npeaks = 0; g_nops = 0;
        g_minf0m_bits = 0x7F800000u;
        g_R = 0; g_tail = 0;
    }
}

__global__ void k_sum(const float* __restrict__ snd, int T) {
    __shared__ double sm[8];
    double s = 0.0;
    for (long long t = blockIdx.x * (long long)blockDim.x + threadIdx.x; t < T;
         t += (long long)gridDim.x * blockDim.x) s += (double)snd[t];
    for (int o = 16; o; o >>= 1) s += __shfl_xor_sync(0xffffffffu, s, o);
    if ((threadIdx.x & 31) == 0) sm[threadIdx.x >> 5] = s;
    __syncthreads();
    if (threadIdx.x == 0) {
        double tot = 0.0;
        int nw = blockDim.x >> 5;
        for (int q = 0; q < nw; q++) tot += sm[q];
        atomicAdd(&g_sum, tot);
    }
}

__global__ void k_mean(int T) {
    if (threadIdx.x == 0 && blockIdx.x == 0) g_meanf = (float)(g_sum / (double)T);
}

// x = snd - mean ; exact f64 interp of pitch -> f0 ; gpeak ; npos ; hist pass 1
__global__ void k_prep(const float* __restrict__ snd, const float* __restrict__ pitch,
                       int T, int S) {
    long long t = blockIdx.x * (long long)blockDim.x + threadIdx.x;
    float f = 0.0f, ax = 0.0f;
    if (t < T) {
        float xv = snd[t] - g_meanf;
        g_x[t] = xv;
        ax = fabsf(xv);
        double pos = ((double)t + 0.5) * ((double)S / (double)T) - 0.5;
        pos = fmin(fmax(pos, 0.0), (double)(S - 1));
        long long lo = (long long)floor(pos);
        long long hi = lo + 1; if (hi > (long long)S - 1) hi = (long long)S - 1;
        double frac = pos - (double)lo;
        double val = (double)pitch[lo] * (1.0 - frac) + (double)pitch[hi] * frac;
        f = (float)val;
        g_f0[t] = f;
    }
    unsigned b = __float_as_uint(ax);
    for (int o = 16; o; o >>= 1) {
        unsigned v = __shfl_xor_sync(0xffffffffu, b, o); if (v > b) b = v;
    }
    if ((threadIdx.x & 31) == 0) atomicMax(&g_gpeak_bits, b);
    bool posq = (t < T) && (f > 0.0f);
    unsigned bal = __ballot_sync(0xffffffffu, posq);
    if ((threadIdx.x & 31) == 0 && bal)
        atomicAdd(&g_npos, (unsigned long long)__popc(bal));
    if (posq) atomicAdd(&g_h1[__float_as_uint(f) >> 12], 1u);
}

__global__ void k_sel1() {
    __shared__ unsigned long long part[1024];
    const int per = H1BINS / 1024;
    unsigned long long s = 0ull;
    int base = threadIdx.x * per;
    for (int j = 0; j < per; j++) s += (unsigned long long)g_h1[base + j];
    part[threadIdx.x] = s;
    __syncthreads();
    if (threadIdx.x == 0) {
        unsigned long long npos = g_npos;
        unsigned long long k = (npos > 0ull) ? (npos - 1ull) / 2ull : 0ull;
        unsigned long long cum = 0ull; int c = 0;
        while (c < 1023 && cum + part[c] <= k) { cum += part[c]; c++; }
        int b = c * per;
        while (b < H1BINS - 1 && cum + (unsigned long long)g_h1[b] <= k) {
            cum += (unsigned long long)g_h1[b]; b++;
        }
        g_h1bin = (unsigned)b;
        g_k2 = k - cum;
        g_gpeak = __uint_as_float(g_gpeak_bits);
    }
}

__global__ void k_hist2(int T) {
    long long t = blockIdx.x * (long long)blockDim.x + threadIdx.x;
    if (t < T) {
        float f = g_f0[t];
        if (f > 0.0f) {
            unsigned b = __float_as_uint(f);
            if ((b >> 12) == g_h1bin) atomicAdd(&g_h2[b & 0xFFFu], 1u);
        }
    }
}

__global__ void k_sel2(const float* __restrict__ psp) {
    if (threadIdx.x == 0 && blockIdx.x == 0) {
        unsigned long long cum = 0ull; int b = 0;
        while (b < H2BINS - 1 && cum + (unsigned long long)g_h2[b] <= g_k2) {
            cum += (unsigned long long)g_h2[b]; b++;
        }
        unsigned bits = (g_h1bin << 12) | (unsigned)b;
        float med0 = __uint_as_float(bits);
        double med = (double)med0 * (double)psp[0];  // python float: float(voiced[k]) * pitch_shift
        g_m32 = (float)med;                          // cast to f32 by NEP-50 array ops
    }
}

// modified f0 (NumPy float32 scalar semantics) + min positive
__global__ void k_f0m(int T, const float* __restrict__ psp, const float* __restrict__ prp) {
    long long t = blockIdx.x * (long long)blockDim.x + threadIdx.x;
    unsigned mb = 0x7F800000u;
    if (t < T) {
        float f = g_f0[t];
        float fs = f * psp[0];          // f32 * f32
        float m = g_m32;
        float o = (fs > 0.0f) ? (m + (fs - m) * prp[0]) : 0.0f;
        g_f0m[t] = o;
        if (o > 0.0f) mb = __float_as_uint(o);
    }
    for (int off = 16; off; off >>= 1) {
        unsigned v = __shfl_xor_sync(0xffffffffu, mb, off); if (v < mb) mb = v;
    }
    if ((threadIdx.x & 31) == 0) atomicMin(&g_minf0m_bits, mb);
}

__global__ void k_regions(int T) {
    long long t = blockIdx.x * (long long)blockDim.x + threadIdx.x;
    if (t >= T) return;
    if (!(g_f0[t] > 0.0f)) return;
    bool vp = (t > 0) ? (g_f0[t - 1] > 0.0f) : false;
    bool vn = (t + 1 < T) ? (g_f0[t + 1] > 0.0f) : false;
    if (!vp) { int q = atomicAdd(&g_nstarts, 1); if (q < MAX_REG) g_starts[q] = (int)t; }
    if (!vn) { int q = atomicAdd(&g_nends, 1);   if (q < MAX_REG) g_ends[q] = (int)(t + 1); }
}

__global__ void k_regsort() {
    if (threadIdx.x != 0 || blockIdx.x != 0) return;
    int ns = g_nstarts; if (ns > MAX_REG) ns = MAX_REG;
    int ne = g_nends;   if (ne > MAX_REG) ne = MAX_REG;
    for (int a = 1; a < ns; a++) {
        int v = g_starts[a]; int b = a - 1;
        while (b >= 0 && g_starts[b] > v) { g_starts[b + 1] = g_starts[b]; b--; }
        g_starts[b + 1] = v;
    }
    for (int a = 1; a < ne; a++) {
        int v = g_ends[a]; int b = a - 1;
        while (b >= 0 && g_ends[b] > v) { g_ends[b + 1] = g_ends[b]; b--; }
        g_ends[b + 1] = v;
    }
    // _find_voiced forces flag[0] = 0: a run starting at index 0 starts at 1
    if (ns > 0 && g_starts[0] == 0) g_starts[0] = 1;
    int n = ns < ne ? ns : ne;
    int R = 0;
    for (int a = 0; a < n; a++) {
        if (g_starts[a] < g_ends[a]) { g_starts[R] = g_starts[a]; g_ends[R] = g_ends[a]; R++; }
    }
    if (R > REG_CAP) R = REG_CAP;
    g_R = R;
    g_tail = (R > 0) ? g_ends[R - 1] : 0;
    g_maxw = 1.25 * 16000.0 / (double)__uint_as_float(g_minf0m_bits);
}

// ------------------------------------------------------------------
// Peak-finding sweeps: one block per (region, direction)
// ------------------------------------------------------------------
#define MAXCAND 168
#define SH_SIG  512
#define SH_TMPL 288

__global__ void __launch_bounds__(256, 2) k_sweep(int T) {
    int reg = blockIdx.x >> 1;
    int dir = blockIdx.x & 1;   // 0 = left, 1 = right
    if (reg >= g_R) return;

    __shared__ float  sh_sig[SH_SIG];
    __shared__ float  sh_tmpl[SH_TMPL];
    __shared__ double sh_corr[MAXCAND];
    __shared__ double red_d[8];
    __shared__ float  red_f[8], red_f2[8];
    __shared__ int    red_i[8], red_i2[8];
    __shared__ int st_i, st_done, st_w, st_cl, st_s, st_nc, st_degen, st_rbest, st_inew, st_lim;
    __shared__ double st_corr;
    __shared__ float st_peak;

    int tid = threadIdx.x, lane = tid & 31, wid = tid >> 5;
    int left = g_starts[reg], right = g_ends[reg];
    float gpeak = g_gpeak;

    // ---- backup = extremum near region middle ----
    int middle = (left + right) >> 1;
    int wm = (int)(16000.0 / (double)g_f0[middle]);   // no floor here (reference)
    int s0 = middle - wm / 2; if (s0 < 0) s0 = 0;
    int wlen = wm; if (s0 + wlen > T) wlen = T - s0;

    float mn = 1e30f;  int imn = 0x7fffffff;
    float mx = -1e30f; int imx = 0x7fffffff;
    for (int j = tid; j < wlen; j += 256) {
        float v = g_x[s0 + j];
        if (v < mn) { mn = v; imn = j; }
        if (v > mx) { mx = v; imx = j; }
    }
    for (int o = 16; o; o >>= 1) {
        float vm = __shfl_xor_sync(0xffffffffu, mn, o);
        int   im = __shfl_xor_sync(0xffffffffu, imn, o);
        if (vm < mn || (vm == mn && im < imn)) { mn = vm; imn = im; }
        float vx = __shfl_xor_sync(0xffffffffu, mx, o);
        int   ix = __shfl_xor_sync(0xffffffffu, imx, o);
        if (vx > mx || (vx == mx && ix < imx)) { mx = vx; imx = ix; }
    }
    if (lane == 0) { red_f[wid] = mn; red_i[wid] = imn; red_f2[wid] = mx; red_i2[wid] = imx; }
    __syncthreads();
    if (tid == 0) {
        float fmn = red_f[0]; int fimn = red_i[0];
        float fmx = red_f2[0]; int fimx = red_i2[0];
        for (int q = 1; q < 8; q++) {
            if (red_f[q] < fmn || (red_f[q] == fmn && red_i[q] < fimn)) { fmn = red_f[q]; fimn = red_i[q]; }
            if (red_f2[q] > fmx || (red_f2[q] == fmx && red_i2[q] < fimx)) { fmx = red_f2[q]; fimx = red_i2[q]; }
        }
        int i0;
        if (fmn == fmx) i0 = middle;
        else i0 = s0 + ((fabsf(fmn) > fabsf(fmx)) ? fimn : fimx);
        st_i = i0; st_done = 0;
    }
    __syncthreads();

    // ---- sweep loop ----
    for (int step = 0; step < 60000; step++) {
        __syncthreads();
        if (tid == 0) {
            int i = st_i;
            double f = fmax((double)g_f0[i], 60.0);
            int w = (int)(16000.0 / f);
            int s = i - w / 2; if (s < 0) s = 0;
            int cl, cr;
            if (dir == 0) {
                cl = (int)((double)i - 1.75 * (double)w); if (cl < 0) cl = 0;
                cr = (int)((double)i - 1.3  * (double)w); if (cr < 0) cr = 0;
            } else {
                cl = (int)((double)i + 0.3  * (double)w);
                cr = (int)((double)i + 0.75 * (double)w);
            }
            int degen = (cl == cr) || (T - cl < w) || (s + w > T);
            st_w = w; st_s = s; st_cl = cl; st_degen = degen;
            if (!degen) {
                int lim = cr + w; if (lim > T) lim = T;
                st_lim = lim;
                int nc = lim - cl - w + 1;
                if (nc > MAXCAND) nc = MAXCAND;  // analysis bound: nc <= 121
                st_nc = nc;
            }
        }
        __syncthreads();
        if (!st_degen) {
            int w = st_w, cl = st_cl, s = st_s, nc = st_nc, lim = st_lim;
            int span = lim - cl;
            for (int j = tid; j < span; j += 256) sh_sig[j] = g_x[cl + j];
            double tp = 0.0;
            for (int j = tid; j < w; j += 256) {
                float tv = g_x[s + j];
                sh_tmpl[j] = tv;
                tp += (double)tv * (double)tv;
            }
            for (int o = 16; o; o >>= 1) tp += __shfl_xor_sync(0xffffffffu, tp, o);
            if (lane == 0) red_d[wid] = tp;
            __syncthreads();
            double tn = 0.0;
            for (int q = 0; q < 8; q++) tn += red_d[q];
            tn = fmax(sqrt(tn), 1e-12);
            for (int r = wid; r < nc; r += 8) {
                double dot = 0.0, nr = 0.0;
                for (int j = lane; j < w; j += 32) {
                    double sv = (double)sh_sig[r + j];
                    double tv = (double)sh_tmpl[j];
                    dot += sv * tv; nr += sv * sv;
                }
                for (int o = 16; o; o >>= 1) {
                    dot += __shfl_xor_sync(0xffffffffu, dot, o);
                    nr  += __shfl_xor_sync(0xffffffffu, nr, o);
                }
                if (lane == 0) sh_corr[r] = dot / (fmax(sqrt(nr), 1e-12) * tn);
            }
            __syncthreads();
            if (tid == 0) {
                double best = sh_corr[0]; int rb = 0;
                for (int r = 1; r < nc; r++)
                    if (sh_corr[r] > best) { best = sh_corr[r]; rb = r; }
                st_rbest = rb; st_corr = best;
                st_inew = st_i + rb + cl - s;
            }
            __syncthreads();
            {
                int rb = st_rbest;
                float pm = 0.0f;
                for (int j = tid; j < w; j += 256) pm = fmaxf(pm, fabsf(sh_sig[rb + j]));
                for (int o = 16; o; o >>= 1)
                    pm = fmaxf(pm, __shfl_xor_sync(0xffffffffu, pm, o));
                if (lane == 0) red_f[wid] = pm;
            }
            __syncthreads();
            if (tid == 0) {
                float pk = 0.0f;
                for (int q = 0; q < 8; q++) pk = fmaxf(pk, red_f[q]);
                st_peak = pk;
            }
        } else {
            if (tid == 0) { st_corr = -1.0; st_inew = st_i; st_peak = 0.0f; }
        }
        __syncthreads();
        if (tid == 0) {
            double corr = st_corr; int w = st_w; float peak = st_peak;
            int i = (corr == -1.0) ? (st_i + (dir ? w : -w)) : st_inew;
            if (dir == 0) {
                if (i < left) {
                    if (corr > 0.7 && (double)peak > 0.023333 * (double)gpeak) {
                        int c = g_lcnt[reg];
                        if (c < PERCAP) { g_lpos[reg][c] = i; g_lw[reg][c] = w; g_lcnt[reg] = c + 1; }
                    }
                    st_done = 1;
                } else if (corr > 0.3 && (peak == 0.0f || (double)peak > 0.01 * (double)gpeak)) {
                    int c = g_lcnt[reg];
                    if (c < PERCAP) { g_lpos[reg][c] = i; g_lw[reg][c] = w; g_lcnt[reg] = c + 1; }
                }
            } else {
                if (i >= right) {
                    if (corr > 0.7 && (double)peak > 0.023333 * (double)gpeak) {
                        int c = g_rcnt[reg];
                        if (c < PERCAP) { g_rpos[reg][c] = i; g_rcnt[reg] = c + 1; }
                    }
                    st_done = 1;
                } else if (corr > 0.3 && (peak == 0.0f || (double)peak > 0.01 * (double)gpeak)) {
                    int c = g_rcnt[reg];
                    if (c < PERCAP) { g_rpos[reg][c] = i; g_rcnt[reg] = c + 1; }
                }
            }
            st_i = i;
        }
        __syncthreads();
        if (st_done) break;
    }
}

// ------------------------------------------------------------------
// Resolve added_right chain, gate left candidates, build sorted peaks
// ------------------------------------------------------------------
__global__ void k_resolve(int T) {
    if (threadIdx.x != 0 || blockIdx.x != 0) return;
    double ar = -1e308;
    int np = 0;
    int R = g_R;
    for (int r = 0; r < R; r++) {
        int lc = g_lcnt[r];
        for (int j = lc - 1; j >= 0; j--) {     // reverse -> ascending positions
            int p = g_lpos[r][j]; int w = g_lw[r][j];
            if ((double)p - ar > 0.8 * (double)w) {
                int pc = p; if (pc < 0) pc = 0; if (pc > T - 1) pc = T - 1;
                if (np < MAX_PEAKS) g_peaks[np++] = pc;
            }
        }
        int rc = g_rcnt[r];
        for (int j = 0; j < rc; j++) {
            int pc = g_rpos[r][j]; if (pc < 0) pc = 0; if (pc > T - 1) pc = T - 1;
            if (np < MAX_PEAKS) g_peaks[np++] = pc;
        }
        if (rc > 0) ar = (double)g_rpos[r][rc - 1];   // raw value (clip happens at end in ref)
    }
    // nearly-sorted insertion sort (O(n) in practice)
    for (int a = 1; a < np; a++) {
        int v = g_peaks[a]; int b = a - 1;
        while (b >= 0 && g_peaks[b] > v) { g_peaks[b + 1] = g_peaks[b]; b--; }
        g_peaks[b + 1] = v;
    }
    g_npeaks = np;
}

// ------------------------------------------------------------------
// PSOLA plan: one thread per region
// ------------------------------------------------------------------
__device__ __forceinline__ int lb_peaks(int np, int v) {
    int lo = 0, hi = np;
    while (lo < hi) { int mid = (lo + hi) >> 1; if (g_peaks[mid] < v) lo = mid + 1; else hi = mid; }
    return lo;
}

__global__ void k_plan(int T) {
    int r = threadIdx.x;
    if (r >= g_R) return;
    int np = g_npeaks;
    int left_v = g_starts[r], right_v = g_ends[r];
    int iprev = (r == 0) ? 0 : g_ends[r - 1];
    int n0 = left_v - iprev;
    if (n0 > 0) {
        int idx = atomicAdd(&g_nops, 1);
        if (idx < MAX_OPS) g_ops[idx] = make_int4(iprev, iprev, n0, n0);
    }
    if (np == 0) return;
    double maxw = g_maxw;
    int guard = 0;
    while (left_v < right_v && guard++ < 2000000) {
        // argmin |peaks - left_v|, numpy first-occurrence
        int p;
        {
            int lb = lb_peaks(np, left_v);
            int p0;
            if (lb == 0) p0 = 0;
            else if (lb == np) p0 = np - 1;
            else {
                long long d1 = (long long)left_v - g_peaks[lb - 1];
                long long d2 = (long long)g_peaks[lb] - left_v;
                p0 = (d2 < d1) ? lb : lb - 1;   // tie -> smaller index side (v-d first)
            }
            p = lb_peaks(np, g_peaks[p0]);      // first occurrence of that value
        }
        int period = (int)(16000.0 / fmax((double)g_f0m[left_v], 60.0));
        int lw = period >> 1, rw = period >> 1;
        if (p > 0) {
            int d = g_peaks[p] - g_peaks[p - 1];
            if ((double)d <= maxw && d < lw) lw = d;
        }
        if (p < np - 1) {
            int d = g_peaks[p + 1] - g_peaks[p];
            if ((double)d <= maxw && d < rw) rw = d;
        }
        int li = g_peaks[p] - lw; if (li < 0) li = 0;
        int ri = g_peaks[p] + rw;
        int ival = (ri - li) >> 1;
        if (ival <= 0) { int st = period > 1 ? period : 1; left_v += st; continue; }
        int a = left_v - ival, b = left_v + ival;
        if (a >= 0) {      // a<0 -> python slice wrap -> zero-length op in reference
            int sp = b < T ? b : T;
            int dst_len = sp - a; if (dst_len < 0) dst_len = 0;
            int se = li + 2 * ival; if (se > T) se = T;
            int src_len = se - li;
            int seglen = dst_len < src_len ? dst_len : src_len;
            if (seglen > 0) {
                int idx = atomicAdd(&g_nops, 1);
                if (idx < MAX_OPS) g_ops[idx] = make_int4(a, li, seglen, 2 * ival);
            }
        }
        left_v += 2 * ival;
    }
}

// ------------------------------------------------------------------
// Output
// ------------------------------------------------------------------
__global__ void k_outzero(float* __restrict__ out, int T) {
    long long t = blockIdx.x * (long long)blockDim.x + threadIdx.x;
    if (t < T) out[t] = 0.0f;
}

__global__ void k_exec(float* __restrict__ out, int T) {
    int nops = g_nops; if (nops > MAX_OPS) nops = MAX_OPS;
    for (int op = blockIdx.x; op < nops; op += gridDim.x) {
        int4 o = g_ops[op];
        int dst = o.x, src = o.y, n = o.z;
        double dn = (double)o.w;
        for (int k = threadIdx.x; k < n; k += blockDim.x) {
            double t = (6.283185307179586 * (double)k) / dn;
            float wk = (float)(0.5 - 0.5 * cos(t));
            atomicAdd(&out[dst + k], wk * g_x[src + k]);
        }
    }
}

__global__ void k_final(float* __restrict__ out, int T) {
    long long t = blockIdx.x * (long long)blockDim.x + threadIdx.x;
    if (t < T) {
        if (t >= g_tail) out[t] = g_x[t];
    }
}

// ------------------------------------------------------------------
// Launch
// ------------------------------------------------------------------
extern "C" void kernel_launch(void* const* d_in, const int* in_sizes, int n_in,
                              void* d_out, int out_size) {
    const float* snd   = (const float*)d_in[0];
    const float* pitch = (const float*)d_in[1];
    const float* ps    = (const float*)d_in[2];
    const float* pr    = (const float*)d_in[3];
    float* out = (float*)d_out;
    int T = in_sizes[0];
    int S = in_sizes[1];
    if (T > MAX_T) T = MAX_T;
    int gridT = (T + 255) / 256;

    k_init<<<64, 256>>>();
    k_sum<<<512, 256>>>(snd, T);
    k_mean<<<1, 1>>>(T);
    k_prep<<<gridT, 256>>>(snd, pitch, T, S);
    k_sel1<<<1, 1024>>>();
    k_hist2<<<gridT, 256>>>(T);
    k_sel2<<<1, 1>>>(ps);
    k_f0m<<<gridT, 256>>>(T, ps, pr);
    k_regions<<<gridT, 256>>>(T);
    k_regsort<<<1, 1>>>();
    k_sweep<<<2 * REG_CAP, 256>>>(T);
    k_resolve<<<1, 1>>>(T);
    k_plan<<<1, REG_CAP>>>(T);
    k_outzero<<<gridT, 256>>>(out, T);
    k_exec<<<2048, 128>>>(out, T);
    k_final<<<gridT, 256>>>(out, T);
}

// round 16
// speedup vs baseline: 1.7067x; 1.7067x over previous
#include <cuda_runtime.h>
#include <cuda_bf16.h>
#include <math.h>

// ------------------------------------------------------------------
// Static scratch (no allocations allowed anywhere)
// ------------------------------------------------------------------
#define MAX_T     3900000
#define MAX_REG   1024
#define REG_CAP   128
#define PERCAP    6144
#define MAX_PEAKS 131072
#define MAX_OPS   (1<<18)
#define H1BINS    (1<<19)
#define H2BINS    (1<<12)

__device__ float g_x[MAX_T];
__device__ float g_f0[MAX_T];
__device__ float g_f0m[MAX_T];

__device__ unsigned g_h1[H1BINS];
__device__ unsigned g_h2[H2BINS];

__device__ double   g_sum;
__device__ float    g_meanf;
__device__ unsigned g_gpeak_bits;
__device__ float    g_gpeak;
__device__ unsigned long long g_npos;
__device__ unsigned g_h1bin;
__device__ unsigned long long g_k2;
__device__ float    g_m32;
__device__ unsigned g_minf0m_bits;
__device__ double   g_maxw;

__device__ int g_nstarts, g_nends;
__device__ int g_starts[MAX_REG], g_ends[MAX_REG];
__device__ int g_R;
__device__ int g_tail;

__device__ int g_lcnt[REG_CAP];
__device__ int g_rcnt[REG_CAP];
__device__ int g_lpos[REG_CAP][PERCAP];
__device__ int g_lw[REG_CAP][PERCAP];
__device__ int g_rpos[REG_CAP][PERCAP];

__device__ double g_ar_in[REG_CAP];
__device__ int    g_lgate[REG_CAP][PERCAP];
__device__ int    g_lgcnt[REG_CAP];
__device__ int    g_off[REG_CAP];
__device__ int    g_sortbad;

__device__ int g_npeaks;
__device__ int g_peaks[MAX_PEAKS];

__device__ int  g_nops;
__device__ int4 g_ops[MAX_OPS];   // (dst0, src0, n, hann_len)

// ------------------------------------------------------------------
// Elementwise / reduction kernels
// ------------------------------------------------------------------
__global__ void k_init() {
    int i = blockIdx.x * blockDim.x + threadIdx.x;
    int stride = gridDim.x * blockDim.x;
    for (int j = i; j < H1BINS; j += stride) g_h1[j] = 0u;
    for (int j = i; j < H2BINS; j += stride) g_h2[j] = 0u;
    for (int j = i; j < REG_CAP; j += stride) { g_lcnt[j] = 0; g_rcnt[j] = 0; g_lgcnt[j] = 0; }
    if (i == 0) {
        g_sum = 0.0; g_gpeak_bits = 0u; g_npos = 0ull;
        g_nstarts = 0; g_nends = 0; g_npeaks = 0; g_nops = 0;
        g_minf0m_bits = 0x7F800000u;
        g_R = 0; g_tail = 0; g_sortbad = 0;
    }
}

__global__ void k_sum(const float* __restrict__ snd, int T) {
    __shared__ double sm[8];
    double s = 0.0;
    for (long long t = blockIdx.x * (long long)blockDim.x + threadIdx.x; t < T;
         t += (long long)gridDim.x * blockDim.x) s += (double)snd[t];
    for (int o = 16; o; o >>= 1) s += __shfl_xor_sync(0xffffffffu, s, o);
    if ((threadIdx.x & 31) == 0) sm[threadIdx.x >> 5] = s;
    __syncthreads();
    if (threadIdx.x == 0) {
        double tot = 0.0;
        int nw = blockDim.x >> 5;
        for (int q = 0; q < nw; q++) tot += sm[q];
        atomicAdd(&g_sum, tot);
    }
}

__global__ void k_mean(int T) {
    if (threadIdx.x == 0 && blockIdx.x == 0) g_meanf = (float)(g_sum / (double)T);
}

// x = snd - mean ; exact f64 interp of pitch -> f0 ; gpeak ; npos ; hist pass 1
__global__ void k_prep(const float* __restrict__ snd, const float* __restrict__ pitch,
                       int T, int S) {
    long long t = blockIdx.x * (long long)blockDim.x + threadIdx.x;
    float f = 0.0f, ax = 0.0f;
    if (t < T) {
        float xv = snd[t] - g_meanf;
        g_x[t] = xv;
        ax = fabsf(xv);
        double pos = ((double)t + 0.5) * ((double)S / (double)T) - 0.5;
        pos = fmin(fmax(pos, 0.0), (double)(S - 1));
        long long lo = (long long)floor(pos);
        long long hi = lo + 1; if (hi > (long long)S - 1) hi = (long long)S - 1;
        double frac = pos - (double)lo;
        double val = (double)pitch[lo] * (1.0 - frac) + (double)pitch[hi] * frac;
        f = (float)val;
        g_f0[t] = f;
    }
    unsigned b = __float_as_uint(ax);
    for (int o = 16; o; o >>= 1) {
        unsigned v = __shfl_xor_sync(0xffffffffu, b, o); if (v > b) b = v;
    }
    if ((threadIdx.x & 31) == 0) atomicMax(&g_gpeak_bits, b);
    bool posq = (t < T) && (f > 0.0f);
    unsigned bal = __ballot_sync(0xffffffffu, posq);
    if ((threadIdx.x & 31) == 0 && bal)
        atomicAdd(&g_npos, (unsigned long long)__popc(bal));
    if (posq) atomicAdd(&g_h1[__float_as_uint(f) >> 12], 1u);
}

__global__ void k_sel1() {
    __shared__ unsigned long long part[1024];
    const int per = H1BINS / 1024;
    unsigned long long s = 0ull;
    int base = threadIdx.x * per;
    for (int j = 0; j < per; j++) s += (unsigned long long)g_h1[base + j];
    part[threadIdx.x] = s;
    __syncthreads();
    if (threadIdx.x == 0) {
        unsigned long long npos = g_npos;
        unsigned long long k = (npos > 0ull) ? (npos - 1ull) / 2ull : 0ull;
        unsigned long long cum = 0ull; int c = 0;
        while (c < 1023 && cum + part[c] <= k) { cum += part[c]; c++; }
        int b = c * per;
        while (b < H1BINS - 1 && cum + (unsigned long long)g_h1[b] <= k) {
            cum += (unsigned long long)g_h1[b]; b++;
        }
        g_h1bin = (unsigned)b;
        g_k2 = k - cum;
        g_gpeak = __uint_as_float(g_gpeak_bits);
    }
}

__global__ void k_hist2(int T) {
    long long t = blockIdx.x * (long long)blockDim.x + threadIdx.x;
    if (t < T) {
        float f = g_f0[t];
        if (f > 0.0f) {
            unsigned b = __float_as_uint(f);
            if ((b >> 12) == g_h1bin) atomicAdd(&g_h2[b & 0xFFFu], 1u);
        }
    }
}

__global__ void k_sel2(const float* __restrict__ psp) {
    if (threadIdx.x == 0 && blockIdx.x == 0) {
        unsigned long long cum = 0ull; int b = 0;
        while (b < H2BINS - 1 && cum + (unsigned long long)g_h2[b] <= g_k2) {
            cum += (unsigned long long)g_h2[b]; b++;
        }
        unsigned bits = (g_h1bin << 12) | (unsigned)b;
        float med0 = __uint_as_float(bits);
        double med = (double)med0 * (double)psp[0];  // python float
        g_m32 = (float)med;
    }
}

// fused: modified f0 (NumPy float32 semantics) + min positive + region boundaries
__global__ void k_f0m_regions(int T, const float* __restrict__ psp, const float* __restrict__ prp) {
    long long t = blockIdx.x * (long long)blockDim.x + threadIdx.x;
    unsigned mb = 0x7F800000u;
    if (t < T) {
        float f = g_f0[t];
        float fs = f * psp[0];
        float m = g_m32;
        float o = (fs > 0.0f) ? (m + (fs - m) * prp[0]) : 0.0f;
        g_f0m[t] = o;
        if (o > 0.0f) mb = __float_as_uint(o);
        if (f > 0.0f) {
            bool vp = (t > 0) ? (g_f0[t - 1] > 0.0f) : false;
            bool vn = (t + 1 < T) ? (g_f0[t + 1] > 0.0f) : false;
            if (!vp) { int q = atomicAdd(&g_nstarts, 1); if (q < MAX_REG) g_starts[q] = (int)t; }
            if (!vn) { int q = atomicAdd(&g_nends, 1);   if (q < MAX_REG) g_ends[q] = (int)(t + 1); }
        }
    }
    for (int off = 16; off; off >>= 1) {
        unsigned v = __shfl_xor_sync(0xffffffffu, mb, off); if (v < mb) mb = v;
    }
    if ((threadIdx.x & 31) == 0) atomicMin(&g_minf0m_bits, mb);
}

__global__ void k_regsort() {
    if (threadIdx.x != 0 || blockIdx.x != 0) return;
    int ns = g_nstarts; if (ns > MAX_REG) ns = MAX_REG;
    int ne = g_nends;   if (ne > MAX_REG) ne = MAX_REG;
    for (int a = 1; a < ns; a++) {
        int v = g_starts[a]; int b = a - 1;
        while (b >= 0 && g_starts[b] > v) { g_starts[b + 1] = g_starts[b]; b--; }
        g_starts[b + 1] = v;
    }
    for (int a = 1; a < ne; a++) {
        int v = g_ends[a]; int b = a - 1;
        while (b >= 0 && g_ends[b] > v) { g_ends[b + 1] = g_ends[b]; b--; }
        g_ends[b + 1] = v;
    }
    if (ns > 0 && g_starts[0] == 0) g_starts[0] = 1;  // _find_voiced flag[0]=0
    int n = ns < ne ? ns : ne;
    int R = 0;
    for (int a = 0; a < n; a++) {
        if (g_starts[a] < g_ends[a]) { g_starts[R] = g_starts[a]; g_ends[R] = g_ends[a]; R++; }
    }
    if (R > REG_CAP) R = REG_CAP;
    g_R = R;
    g_tail = (R > 0) ? g_ends[R - 1] : 0;
    g_maxw = 1.25 * 16000.0 / (double)__uint_as_float(g_minf0m_bits);
}

// ------------------------------------------------------------------
// Peak-finding sweeps: one block per (region, direction)
// thread-per-candidate, FP64 accumulation (matches R14 numerics), 4 syncs/step
// ------------------------------------------------------------------
#define SH_SIG  512
#define SH_TMPL 288

__global__ void __launch_bounds__(256, 2) k_sweep(int T) {
    int reg = blockIdx.x >> 1;
    int dir = blockIdx.x & 1;   // 0 = left, 1 = right
    if (reg >= g_R) return;

    __shared__ float  sh_sig[SH_SIG];
    __shared__ float  sh_tmpl[SH_TMPL];
    __shared__ double red_d[8];
    __shared__ double red_c[8];
    __shared__ int    red_r[8];
    __shared__ float  red_p[8];
    __shared__ float  red_f[8], red_f2[8];
    __shared__ int    red_i[8], red_i2[8];
    __shared__ int st_i, st_done, st_w, st_cl, st_s, st_nc, st_degen;

    int tid = threadIdx.x, lane = tid & 31, wid = tid >> 5;
    int left = g_starts[reg], right = g_ends[reg];
    float gpeak = g_gpeak;

    // ---- backup = extremum near region middle ----
    int middle = (left + right) >> 1;
    int wm = (int)(16000.0 / (double)g_f0[middle]);   // no floor here (reference)
    int s0 = middle - wm / 2; if (s0 < 0) s0 = 0;
    int wlen = wm; if (s0 + wlen > T) wlen = T - s0;

    float mn = 1e30f;  int imn = 0x7fffffff;
    float mx = -1e30f; int imx = 0x7fffffff;
    for (int j = tid; j < wlen; j += 256) {
        float v = g_x[s0 + j];
        if (v < mn) { mn = v; imn = j; }
        if (v > mx) { mx = v; imx = j; }
    }
    for (int o = 16; o; o >>= 1) {
        float vm = __shfl_xor_sync(0xffffffffu, mn, o);
        int   im = __shfl_xor_sync(0xffffffffu, imn, o);
        if (vm < mn || (vm == mn && im < imn)) { mn = vm; imn = im; }
        float vx = __shfl_xor_sync(0xffffffffu, mx, o);
        int   ix = __shfl_xor_sync(0xffffffffu, imx, o);
        if (vx > mx || (vx == mx && ix < imx)) { mx = vx; imx = ix; }
    }
    if (lane == 0) { red_f[wid] = mn; red_i[wid] = imn; red_f2[wid] = mx; red_i2[wid] = imx; }
    __syncthreads();
    if (tid == 0) {
        float fmn = red_f[0]; int fimn = red_i[0];
        float fmx = red_f2[0]; int fimx = red_i2[0];
        for (int q = 1; q < 8; q++) {
            if (red_f[q] < fmn || (red_f[q] == fmn && red_i[q] < fimn)) { fmn = red_f[q]; fimn = red_i[q]; }
            if (red_f2[q] > fmx || (red_f2[q] == fmx && red_i2[q] < fimx)) { fmx = red_f2[q]; fimx = red_i2[q]; }
        }
        int i0;
        if (fmn == fmx) i0 = middle;
        else i0 = s0 + ((fabsf(fmn) > fabsf(fmx)) ? fimn : fimx);
        st_i = i0; st_done = 0;
    }
    __syncthreads();

    // ---- sweep loop ----
    for (int step = 0; step < 60000; step++) {
        if (tid == 0) {
            int i = st_i;
            double f = fmax((double)g_f0[i], 60.0);
            int w = (int)(16000.0 / f);
            int s = i - w / 2; if (s < 0) s = 0;
            int cl, cr;
            if (dir == 0) {
                cl = (int)((double)i - 1.75 * (double)w); if (cl < 0) cl = 0;
                cr = (int)((double)i - 1.3  * (double)w); if (cr < 0) cr = 0;
            } else {
                cl = (int)((double)i + 0.3  * (double)w);
                cr = (int)((double)i + 0.75 * (double)w);
            }
            int degen = (cl == cr) || (T - cl < w) || (s + w > T);
            st_w = w; st_s = s; st_cl = cl; st_degen = degen;
            if (!degen) {
                int lim = cr + w; if (lim > T) lim = T;
                int nc = lim - cl - w + 1;
                if (nc > 256) nc = 256;
                st_nc = nc;
            }
        }
        __syncthreads();               // (1) params published
        if (!st_degen) {
            int w = st_w, cl = st_cl, s = st_s, nc = st_nc;
            int span = nc - 1 + w;
            for (int j = tid; j < span; j += 256) sh_sig[j] = g_x[cl + j];
            // template tile + fp64 norm partials
            double tp = 0.0;
            for (int j = tid; j < w; j += 256) {
                float tv = g_x[s + j];
                sh_tmpl[j] = tv;
                tp += (double)tv * (double)tv;
            }
            for (int o = 16; o; o >>= 1) tp += __shfl_xor_sync(0xffffffffu, tp, o);
            if (lane == 0) red_d[wid] = tp;
            __syncthreads();           // (2) tiles + norm partials ready

            double tn = 0.0;
            for (int q = 0; q < 8; q++) tn += red_d[q];
            tn = fmax(sqrt(tn), 1e-12);

            double bc = -1e300; int br = tid; float bp = 0.0f;
            if (tid < nc) {
                double dot = 0.0, nr = 0.0;
                float pk = 0.0f;
                for (int j = 0; j < w; j++) {
                    float svf = sh_sig[tid + j];
                    double sv = (double)svf;
                    double tv = (double)sh_tmpl[j];
                    dot += sv * tv;
                    nr  += sv * sv;
                    pk = fmaxf(pk, fabsf(svf));
                }
                bc = dot / (fmax(sqrt(nr), 1e-12) * tn);
                bp = pk;
            }
            // argmax, tie -> smallest r (numpy first occurrence)
            for (int o = 16; o; o >>= 1) {
                double oc = __shfl_xor_sync(0xffffffffu, bc, o);
                int   orr = __shfl_xor_sync(0xffffffffu, br, o);
                float op  = __shfl_xor_sync(0xffffffffu, bp, o);
                if (oc > bc || (oc == bc && orr < br)) { bc = oc; br = orr; bp = op; }
            }
            if (lane == 0) { red_c[wid] = bc; red_r[wid] = br; red_p[wid] = bp; }
            __syncthreads();           // (3) warp winners
            if (tid == 0) {
                double c = red_c[0]; int r = red_r[0]; float pk = red_p[0];
                for (int q = 1; q < 8; q++) {
                    if (red_c[q] > c || (red_c[q] == c && red_r[q] < r)) {
                        c = red_c[q]; r = red_r[q]; pk = red_p[q];
                    }
                }
                double corr = c;
                int w2 = st_w;
                int i = st_i + r + st_cl - st_s;
                float peak = pk;
                if (dir == 0) {
                    if (i < left) {
                        if (corr > 0.7 && (double)peak > 0.023333 * (double)gpeak) {
                            int cc = g_lcnt[reg];
                            if (cc < PERCAP) { g_lpos[reg][cc] = i; g_lw[reg][cc] = w2; g_lcnt[reg] = cc + 1; }
                        }
                        st_done = 1;
                    } else if (corr > 0.3 && (peak == 0.0f || (double)peak > 0.01 * (double)gpeak)) {
                        int cc = g_lcnt[reg];
                        if (cc < PERCAP) { g_lpos[reg][cc] = i; g_lw[reg][cc] = w2; g_lcnt[reg] = cc + 1; }
                    }
                } else {
                    if (i >= right) {
                        if (corr > 0.7 && (double)peak > 0.023333 * (double)gpeak) {
                            int cc = g_rcnt[reg];
                            if (cc < PERCAP) { g_rpos[reg][cc] = i; g_rcnt[reg] = cc + 1; }
                        }
                        st_done = 1;
                    } else if (corr > 0.3 && (peak == 0.0f || (double)peak > 0.01 * (double)gpeak)) {
                        int cc = g_rcnt[reg];
                        if (cc < PERCAP) { g_rpos[reg][cc] = i; g_rcnt[reg] = cc + 1; }
                    }
                }
                st_i = i;
            }
        } else {
            // degenerate: corr = -1 -> move by w, boundary check (appends impossible)
            if (tid == 0) {
                int i = st_i + (dir ? st_w : -st_w);
                if (dir == 0) { if (i < left) st_done = 1; }
                else          { if (i >= right) st_done = 1; }
                st_i = i;
            }
        }
        __syncthreads();               // (4) decision published
        if (st_done) break;
    }
}

// ------------------------------------------------------------------
// added_right inputs per region (tiny serial), then parallel gate
// ------------------------------------------------------------------
__global__ void k_arin() {
    if (threadIdx.x != 0 || blockIdx.x != 0) return;
    double ar = -1e308;
    int R = g_R;
    for (int r = 0; r < R; r++) {
        g_ar_in[r] = ar;
        int rc = g_rcnt[r];
        if (rc > 0) ar = (double)g_rpos[r][rc - 1];
    }
}

__global__ void k_gate() {
    int reg = blockIdx.x;
    if (reg >= g_R) return;
    __shared__ int cnts[256];
    __shared__ int offs[256];
    int tid = threadIdx.x;
    int lc = g_lcnt[reg];
    double ar = g_ar_in[reg];
    int chunk = (lc + 255) >> 8;
    int k0 = tid * chunk;
    int k1 = k0 + chunk; if (k1 > lc) k1 = lc;
    if (k0 > lc) k0 = lc;
    int cnt = 0;
    for (int k = k0; k < k1; k++) {       // output order k = lc-1-j (ascending pos)
        int j = lc - 1 - k;
        int p = g_lpos[reg][j]; int w = g_lw[reg][j];
        if ((double)p - ar > 0.8 * (double)w) cnt++;
    }
    cnts[tid] = cnt;
    __syncthreads();
    if (tid == 0) {
        int acc = 0;
        for (int q = 0; q < 256; q++) { offs[q] = acc; acc += cnts[q]; }
        g_lgcnt[reg] = acc;
    }
    __syncthreads();
    int o = offs[tid];
    for (int k = k0; k < k1; k++) {
        int j = lc - 1 - k;
        int p = g_lpos[reg][j]; int w = g_lw[reg][j];
        if ((double)p - ar > 0.8 * (double)w) g_lgate[reg][o++] = p;
    }
}

__global__ void k_offsets() {
    if (threadIdx.x != 0 || blockIdx.x != 0) return;
    int off = 0;
    int R = g_R;
    for (int r = 0; r < R; r++) {
        g_off[r] = off;
        off += g_lgcnt[r] + g_rcnt[r];
        if (off > MAX_PEAKS) off = MAX_PEAKS;
    }
    g_npeaks = off;
}

__global__ void k_scatter(int T) {
    int reg = blockIdx.x;
    if (reg >= g_R) return;
    int base = g_off[reg];
    int lg = g_lgcnt[reg];
    int rc = g_rcnt[reg];
    for (int k = threadIdx.x; k < lg; k += blockDim.x) {
        int p = g_lgate[reg][k];
        if (p < 0) p = 0; if (p > T - 1) p = T - 1;
        int q = base + k; if (q < MAX_PEAKS) g_peaks[q] = p;
    }
    for (int k = threadIdx.x; k < rc; k += blockDim.x) {
        int p = g_rpos[reg][k];
        if (p < 0) p = 0; if (p > T - 1) p = T - 1;
        int q = base + lg + k; if (q < MAX_PEAKS) g_peaks[q] = p;
    }
}

__global__ void k_sortcheck() {
    int np = g_npeaks;
    for (int i = blockIdx.x * blockDim.x + threadIdx.x; i + 1 < np;
         i += gridDim.x * blockDim.x) {
        if (g_peaks[i] > g_peaks[i + 1]) atomicExch(&g_sortbad, 1);
    }
}

__global__ void k_sortfix() {   // normally dead; correctness fallback
    if (threadIdx.x != 0 || blockIdx.x != 0) return;
    if (!g_sortbad) return;
    int np = g_npeaks;
    for (int a = 1; a < np; a++) {
        int v = g_peaks[a]; int b = a - 1;
        while (b >= 0 && g_peaks[b] > v) { g_peaks[b + 1] = g_peaks[b]; b--; }
        g_peaks[b + 1] = v;
    }
}

// ------------------------------------------------------------------
// PSOLA plan: one block per region, monotone argmin pointer
// ------------------------------------------------------------------
__global__ void k_plan(int T) {
    int r = blockIdx.x;
    if (threadIdx.x != 0) return;
    if (r >= g_R) return;
    int np = g_npeaks;
    int left_v = g_starts[r], right_v = g_ends[r];
    int iprev = (r == 0) ? 0 : g_ends[r - 1];
    int n0 = left_v - iprev;
    if (n0 > 0) {
        int idx = atomicAdd(&g_nops, 1);
        if (idx < MAX_OPS) g_ops[idx] = make_int4(iprev, iprev, n0, n0);
    }
    if (np == 0) return;
    double maxw = g_maxw;
    int q = 0;                 // monotone first-occurrence argmin pointer
    int guard = 0;
    while (left_v < right_v && guard++ < 2000000) {
        long long v = (long long)left_v;
        while (q < np - 1) {
            long long d1 = (long long)g_peaks[q] - v;     if (d1 < 0) d1 = -d1;
            long long d2 = (long long)g_peaks[q + 1] - v; if (d2 < 0) d2 = -d2;
            if (d2 < d1) q++; else break;
        }
        int p = q;
        int period = (int)(16000.0 / fmax((double)g_f0m[left_v], 60.0));
        int lw = period >> 1, rw = period >> 1;
        if (p > 0) {
            int d = g_peaks[p] - g_peaks[p - 1];
            if ((double)d <= maxw && d < lw) lw = d;
        }
        if (p < np - 1) {
            int d = g_peaks[p + 1] - g_peaks[p];
            if ((double)d <= maxw && d < rw) rw = d;
        }
        int li = g_peaks[p] - lw; if (li < 0) li = 0;
        int ri = g_peaks[p] + rw;
        int ival = (ri - li) >> 1;
        if (ival <= 0) { int st = period > 1 ? period : 1; left_v += st; continue; }
        int a = left_v - ival, b = left_v + ival;
        if (a >= 0) {          // a<0 -> python slice wrap -> zero-length in reference
            int sp = b < T ? b : T;
            int dst_len = sp - a; if (dst_len < 0) dst_len = 0;
            int se = li + 2 * ival; if (se > T) se = T;
            int src_len = se - li;
            int seglen = dst_len < src_len ? dst_len : src_len;
            if (seglen > 0) {
                int idx = atomicAdd(&g_nops, 1);
                if (idx < MAX_OPS) g_ops[idx] = make_int4(a, li, seglen, 2 * ival);
            }
        }
        left_v += 2 * ival;
    }
}

// ------------------------------------------------------------------
// Output
// ------------------------------------------------------------------
__global__ void k_outinit(float* __restrict__ out, int T) {
    long long t = blockIdx.x * (long long)blockDim.x + threadIdx.x;
    if (t < T) out[t] = (t >= (long long)g_tail) ? g_x[t] : 0.0f;
}

__global__ void k_exec(float* __restrict__ out, int T) {
    int nops = g_nops; if (nops > MAX_OPS) nops = MAX_OPS;
    int tail = g_tail;
    for (int op = blockIdx.x; op < nops; op += gridDim.x) {
        int4 o = g_ops[op];
        int dst = o.x, src = o.y, n = o.z;
        double dn = (double)o.w;
        for (int k = threadIdx.x; k < n; k += blockDim.x) {
            int d = dst + k;
            if (d < tail) {   // adds beyond tail are overwritten by x anyway
                double t = (6.283185307179586 * (double)k) / dn;
                float wk = (float)(0.5 - 0.5 * cos(t));
                atomicAdd(&out[d], wk * g_x[src + k]);
            }
        }
    }
}

// ------------------------------------------------------------------
// Launch
// ------------------------------------------------------------------
extern "C" void kernel_launch(void* const* d_in, const int* in_sizes, int n_in,
                              void* d_out, int out_size) {
    const float* snd   = (const float*)d_in[0];
    const float* pitch = (const float*)d_in[1];
    const float* ps    = (const float*)d_in[2];
    const float* pr    = (const float*)d_in[3];
    float* out = (float*)d_out;
    int T = in_sizes[0];
    int S = in_sizes[1];
    if (T > MAX_T) T = MAX_T;
    int gridT = (T + 255) / 256;

    k_init<<<64, 256>>>();
    k_sum<<<512, 256>>>(snd, T);
    k_mean<<<1, 1>>>(T);
    k_prep<<<gridT, 256>>>(snd, pitch, T, S);
    k_sel1<<<1, 1024>>>();
    k_hist2<<<gridT, 256>>>(T);
    k_sel2<<<1, 1>>>(ps);
    k_f0m_regions<<<gridT, 256>>>(T, ps, pr);
    k_regsort<<<1, 1>>>();
    k_sweep<<<2 * REG_CAP, 256>>>(T);
    k_arin<<<1, 1>>>();
    k_gate<<<REG_CAP, 256>>>();
    k_offsets<<<1, 1>>>();
    k_scatter<<<REG_CAP, 256>>>(T);
    k_sortcheck<<<128, 256>>>();
    k_sortfix<<<1, 1>>>();
    k_plan<<<REG_CAP, 32>>>(T);
    k_outinit<<<gridT, 256>>>(out, T);
    k_exec<<<2048, 128>>>(out, T);
}